// round 1
// baseline (speedup 1.0000x reference)
#include <cuda_runtime.h>
#include <math.h>

#define B_ 8
#define H_ 128
#define W_ 128
#define G_ 64
#define C_ 20

// ---------------- device scratch (no allocations allowed) ----------------
__device__ float         d_Ey[B_][H_][G_];
__device__ float         d_Ex[B_][W_][G_];
__device__ unsigned      d_kp[B_][H_][W_];
__device__ float4        d_box[B_][G_];         // bx1, bx2, by1, by2  (feature-map coords)
__device__ unsigned char d_order[B_][G_];       // valid gts sorted by class (seg)
__device__ int           d_start[B_][C_ + 2];   // bucket starts, [C_+1] = n_valid
__device__ int           d_nv[B_];
__device__ double        d_partial[B_ * H_][6]; // per-row partial sums

// area_pad with forced rounding so pass1/pass2 produce bit-identical values
__device__ __forceinline__ float area_pad_f(float l, float r, float t, float d, float hm) {
    float a1 = __fadd_rn(__fmul_rn(l, hm), __fmul_rn(r, hm));
    float a2 = __fadd_rn(__fmul_rn(t, hm), __fmul_rn(d, hm));
    return __fadd_rn(__fmul_rn(a1, a2), __fmul_rn(__fsub_rn(1.0f, hm), 1e8f));
}

// ---------------- prep: per-image gt params, class buckets, separable gaussians ----------------
__global__ void prep_kernel(const float* __restrict__ gt,
                            const float* __restrict__ sy,
                            const float* __restrict__ sx) {
    int b = blockIdx.x, tid = threadIdx.x;
    __shared__ float scy[G_], scx[G_];
    __shared__ float sfy[G_], sfx[G_], sisy[G_], sisx[G_];
    __shared__ int   sseg[G_];
    __shared__ int   s_nv;

    // zero kp scatter mask for this image
    unsigned* kpf = &d_kp[b][0][0];
    for (int i = tid; i < H_ * W_; i += blockDim.x) kpf[i] = 0u;

    if (tid < G_) {
        const float* g7 = gt + (size_t)(b * G_ + tid) * 7;
        float cy = g7[0], cx = g7[1];
        scy[tid] = cy;
        scx[tid] = cx;
        d_box[b][tid] = make_float4((g7[3] + 0.5f) * 0.25f,   // bx1
                                    (g7[5] + 0.5f) * 0.25f,   // bx2
                                    (g7[2] + 0.5f) * 0.25f,   // by1
                                    (g7[4] + 0.5f) * 0.25f);  // by2
        sfy[tid]  = floorf((cy + 0.5f) * 0.25f);
        sfx[tid]  = floorf((cx + 0.5f) * 0.25f);
        sisy[tid] = 0.5f / sy[b * G_ + tid];
        sisx[tid] = 0.5f / sx[b * G_ + tid];
        int cid = (int)g7[6] - 1;
        sseg[tid] = (cid >= 0 && cid < C_) ? cid : C_;
    }
    __syncthreads();

    if (tid == 0) {
        // slice_index = argmin (first occurrence) of gt[:,0]
        float mn = scy[0]; int am = 0;
        for (int g = 1; g < G_; g++) if (scy[g] < mn) { mn = scy[g]; am = g; }
        s_nv = am;
        d_nv[b] = am;
        // counting sort of valid gts by seg
        int cnt[C_ + 1];
        for (int c = 0; c <= C_; c++) cnt[c] = 0;
        for (int g = 0; g < am; g++) cnt[sseg[g]]++;
        int start[C_ + 2];
        start[0] = 0;
        for (int c = 0; c <= C_; c++) start[c + 1] = start[c] + cnt[c];
        for (int c = 0; c <= C_ + 1 && c < C_ + 2; c++) d_start[b][c] = start[c];
        int pos[C_ + 1];
        for (int c = 0; c <= C_; c++) pos[c] = start[c];
        for (int g = 0; g < am; g++) d_order[b][pos[sseg[g]]++] = (unsigned char)g;
        // gt_kp scatter (serial, <=64 points)
        for (int g = 0; g < am; g++) {
            int sg = sseg[g];
            if (sg < C_) {
                int ky = (int)floorf(scy[g] * 0.25f);
                int kx = (int)floorf(scx[g] * 0.25f);
                ky = min(max(ky, 0), H_ - 1);
                kx = min(max(kx, 0), W_ - 1);
                d_kp[b][ky][kx] |= (1u << sg);
            }
        }
    }
    __syncthreads();

    int nv = s_nv;
    // separable gaussian tables (0 for invalid g == vf factor)
    for (int i = tid; i < H_ * G_; i += blockDim.x) {
        int y = i >> 6, g = i & 63;
        float ey = 0.f, ex = 0.f;
        if (g < nv) {
            float dy = (float)y - sfy[g];
            float dx = (float)y - sfx[g];   // same index doubles as x (H_==W_)
            ey = __expf(-dy * dy * sisy[g]);
            ex = __expf(-dx * dx * sisx[g]);
        }
        d_Ey[b][y][g] = ey;
        d_Ex[b][y][g] = ex;
    }
}

// ---------------- main: per-pixel loss terms, one block per (b, y) row ----------------
__global__ __launch_bounds__(128) void main_kernel(const float* __restrict__ kpt,
                                                   const float* __restrict__ preg,
                                                   const float* __restrict__ fpn,
                                                   const float* __restrict__ masks) {
    int bid = blockIdx.x;
    int b = bid >> 7, y = bid & 127;
    int x = threadIdx.x;

    __shared__ float         sm[W_ * (G_ + 1)];   // masks row, [x][g] padded (conflict-free)
    __shared__ float4        sbox[G_];
    __shared__ float         sEy[G_];
    __shared__ unsigned char sorder[G_];
    __shared__ int           sstart[C_ + 2];
    __shared__ int           s_nv;
    __shared__ double        sacc[6][4];

    const float4* mrow = reinterpret_cast<const float4*>(masks + ((size_t)(b * H_ + y) * W_) * G_);
#pragma unroll
    for (int i = x; i < W_ * G_ / 4; i += 128) {
        float4 v = mrow[i];
        int xx = i >> 4, g0 = (i & 15) << 2;
        float* p = &sm[xx * (G_ + 1) + g0];
        p[0] = v.x; p[1] = v.y; p[2] = v.z; p[3] = v.w;
    }
    if (x < G_) { sbox[x] = d_box[b][x]; sEy[x] = d_Ey[b][y][x]; sorder[x] = d_order[b][x]; }
    if (x < C_ + 2) sstart[x] = d_start[b][x];
    if (x == 0) s_nv = d_nv[b];
    __syncthreads();

    int nv = s_nv;
    float xg = x + 0.5f, yg = y + 0.5f;
    const float* smx = &sm[x * (G_ + 1)];

    // ---- pass 1: loc and area_min ----
    float area_min = (nv < G_) ? 1e8f : 3.402823466e38f;
    float loc = 0.f;
    for (int g = 0; g < nv; g++) {
        float4 bb = sbox[g];
        float l = xg - bb.x, r = bb.y - xg, t = yg - bb.z, d = bb.w - yg;
        float m = smx[g];
        float hm = (l > 0.f && r > 0.f && t > 0.f && d > 0.f) ? m : 0.f;
        loc = fmaxf(loc, hm);
        area_min = fminf(area_min, area_pad_f(l, r, t, d, hm));
    }

    // ---- pass 2: per-class buckets, fused focal losses ----
    float dl = 0, dr = 0, dt = 0, db = 0, iou_red = 0;
    float grav = 0, hpos = 0, hneg = 0, shg = 0;
    unsigned kb = d_kp[b][y][x];
    const float* exrow = &d_Ex[b][x][0];
    size_t pix = (size_t)(b * H_ + y) * W_ + x;
    const float* kpp = kpt + pix * C_;
    const float* fpp = fpn + pix * C_;

    for (int c = 0; c <= C_; c++) {
        float rg = 0.f, hg = 0.f;
        int j0 = sstart[c], j1 = sstart[c + 1];
        for (int j = j0; j < j1; j++) {
            int g = sorder[j];
            float4 bb = sbox[g];
            float l = xg - bb.x, r = bb.y - xg, t = yg - bb.z, d = bb.w - yg;
            float m = smx[g];
            float hm = (l > 0.f && r > 0.f && t > 0.f && d > 0.f) ? m : 0.f;
            float ap = area_pad_f(l, r, t, d, hm);
            float dm = (ap == area_min) ? loc : 0.f;
            dl = fmaxf(dl, l * hm * dm);
            dr = fmaxf(dr, r * hm * dm);
            dt = fmaxf(dt, t * hm * dm);
            db = fmaxf(db, d * hm * dm);
            float red = sEy[g] * __ldg(&exrow[g]);
            iou_red = fmaxf(iou_red, red);
            rg = fmaxf(rg, red);
            hg = fmaxf(hg, dm);
        }
        if (c < C_) {
            // gravity focal (keypoints)
            float p  = fminf(fmaxf(__ldg(&kpp[c]), -30.f), 30.f);
            float e1 = __expf(-p);
            float L1 = __logf(1.f + e1);              // -log_sigmoid(p)
            float iv = __fdividef(1.f, 1.f + e1);     // sigmoid(p)
            float om = e1 * iv;                       // 1 - sigmoid(p)
            float q  = 1.f - rg; q = q * q; q = q * q;
            float neg = q * iv * iv * (p + L1);       // -(1-rg)^4 s^2 log(1-s)
            float pos = om * om * L1;                 // -(1-s)^2 log_sigmoid
            grav += ((kb >> c) & 1u) ? pos : neg;
            // heatmap focal (fpn)
            float f   = fminf(fmaxf(__ldg(&fpp[c]), -30.f), 30.f);
            float e2  = __expf(-f);
            float L2  = __logf(1.f + e2);
            float iv2 = __fdividef(1.f, 1.f + e2);
            float om2 = e2 * iv2;
            hpos += om2 * om2 * L2 * hg;
            hneg += iv2 * iv2 * (f + L2);
            shg  += hg;
        }
    }

    // ---- IoU term ----
    const float* pp = preg + pix * 4;
    float pl = pp[0], pr = pp[1], pt = pp[2], pb = pp[3];
    float inter = (fminf(dl, pl) + fminf(dr, pr)) * (fminf(dt, pt) + fminf(db, pb));
    float uni   = (dl + dr) * (dt + db) + (pl + pr) * (pt + pb) - inter;
    float iou   = inter / (uni + 1e-12f);
    float iou_t = -__logf(iou + 1e-12f) * loc * (iou_red * 4.f + 1.f);

    // ---- deterministic block reduction of 6 partials ----
    double v[6] = { (double)iou_t, (double)loc, (double)grav,
                    (double)hpos * 10.0, (double)hneg * 10.0, (double)shg };
#pragma unroll
    for (int off = 16; off; off >>= 1)
#pragma unroll
        for (int k = 0; k < 6; k++) v[k] += __shfl_down_sync(0xffffffffu, v[k], off);
    int w = x >> 5, lane = x & 31;
    if (lane == 0)
#pragma unroll
        for (int k = 0; k < 6; k++) sacc[k][w] = v[k];
    __syncthreads();
    if (x == 0) {
#pragma unroll
        for (int k = 0; k < 6; k++)
            d_partial[bid][k] = sacc[k][0] + sacc[k][1] + sacc[k][2] + sacc[k][3];
    }
}

// ---------------- final: deterministic combine ----------------
__global__ void final_kernel(float* __restrict__ out) {
    int t = threadIdx.x;   // 128 threads, thread t = row t
    __shared__ double sacc[6][4];
    double tot = 0.0;
    for (int b = 0; b < B_; b++) {
        double v[6];
#pragma unroll
        for (int k = 0; k < 6; k++) v[k] = d_partial[b * H_ + t][k];
#pragma unroll
        for (int off = 16; off; off >>= 1)
#pragma unroll
            for (int k = 0; k < 6; k++) v[k] += __shfl_down_sync(0xffffffffu, v[k], off);
        int w = t >> 5, lane = t & 31;
        __syncthreads();
        if (lane == 0)
#pragma unroll
            for (int k = 0; k < 6; k++) sacc[k][w] = v[k];
        __syncthreads();
        if (t == 0) {
            double iouS  = sacc[0][0] + sacc[0][1] + sacc[0][2] + sacc[0][3];
            double slocS = sacc[1][0] + sacc[1][1] + sacc[1][2] + sacc[1][3];
            double gravS = sacc[2][0] + sacc[2][1] + sacc[2][2] + sacc[2][3];
            double hposS = sacc[3][0] + sacc[3][1] + sacc[3][2] + sacc[3][3];
            double hnegS = sacc[4][0] + sacc[4][1] + sacc[4][2] + sacc[4][3];
            double shgS  = sacc[5][0] + sacc[5][1] + sacc[5][2] + sacc[5][3];
            double HWC = (double)(H_ * W_ * C_);
            double hm_loss = hnegS / (HWC - shgS);
            bool cond = (shgS != 0.0);
            double hm2 = hm_loss + hposS / (cond ? shgS : 1.0);
            double safe_loc = (slocS > 0.0) ? slocS : 1.0;
            double iou_out = cond ? (iouS / safe_loc) : 0.0;
            double nvf = (d_nv[b] > 1) ? (double)d_nv[b] : 1.0;
            double grav_out = cond ? (gravS / nvf) : 0.0;
            double total = cond ? (iou_out + grav_out + hm2) : hm_loss;
            tot += total;
        }
    }
    if (t == 0) out[0] = (float)(tot * (1.0 / B_));
}

// ---------------- launch ----------------
extern "C" void kernel_launch(void* const* d_in, const int* in_sizes, int n_in,
                              void* d_out, int out_size) {
    const float* keypoints = (const float*)d_in[0];
    const float* preg      = (const float*)d_in[1];
    const float* fpn       = (const float*)d_in[2];
    const float* gt        = (const float*)d_in[3];
    const float* masks     = (const float*)d_in[4];
    const float* sy        = (const float*)d_in[5];
    const float* sx        = (const float*)d_in[6];
    (void)in_sizes; (void)n_in; (void)out_size;

    prep_kernel<<<B_, 128>>>(gt, sy, sx);
    main_kernel<<<B_ * H_, 128>>>(keypoints, preg, fpn, masks);
    final_kernel<<<1, 128>>>((float*)d_out);
}

// round 2
// speedup vs baseline: 1.8058x; 1.8058x over previous
#include <cuda_runtime.h>
#include <math.h>
#include <float.h>

#define B_ 8
#define H_ 128
#define W_ 128
#define G_ 64
#define C_ 20

// ---------------- device scratch ----------------
__device__ float4        d_box[B_][G_];          // bx1, bx2, by1, by2 (feature coords)
__device__ float         d_sfy[B_][G_], d_sfx[B_][G_];
__device__ float         d_isy[B_][G_], d_isx[B_][G_];
__device__ int           d_seg[B_][G_];          // class id 0..C_ (C_ = invalid)
__device__ unsigned char d_kpy[B_][G_], d_kpx[B_][G_];
__device__ unsigned char d_order[B_][G_];        // valid gts sorted by class
__device__ int           d_start[B_][C_ + 2];
__device__ int           d_nv[B_];
__device__ double        d_partial[B_ * H_][6];

// forced-rounding area so pass1/pass2 are bit-identical (no FMA contraction)
__device__ __forceinline__ float area_pad_f(float l, float r, float t, float d, float hm) {
    float a1 = __fadd_rn(__fmul_rn(l, hm), __fmul_rn(r, hm));
    float a2 = __fadd_rn(__fmul_rn(t, hm), __fmul_rn(d, hm));
    return __fadd_rn(__fmul_rn(a1, a2), __fmul_rn(__fsub_rn(1.0f, hm), 1e8f));
}

// ---------------- prep: per-gt constants + class buckets (parallel, tiny) ----------------
__global__ void prep_kernel(const float* __restrict__ gt,
                            const float* __restrict__ sy,
                            const float* __restrict__ sx) {
    int b = blockIdx.x, g = threadIdx.x;   // 64 threads
    __shared__ float scy[G_];
    __shared__ int   sseg[G_];

    const float* g7 = gt + (size_t)(b * G_ + g) * 7;
    float cy = g7[0], cx = g7[1];
    scy[g] = cy;
    d_box[b][g] = make_float4((g7[3] + 0.5f) * 0.25f,   // bx1
                              (g7[5] + 0.5f) * 0.25f,   // bx2
                              (g7[2] + 0.5f) * 0.25f,   // by1
                              (g7[4] + 0.5f) * 0.25f);  // by2
    d_sfy[b][g] = floorf((cy + 0.5f) * 0.25f);
    d_sfx[b][g] = floorf((cx + 0.5f) * 0.25f);
    d_isy[b][g] = 0.5f / sy[b * G_ + g];
    d_isx[b][g] = 0.5f / sx[b * G_ + g];
    int cid = (int)g7[6] - 1;
    int seg = (cid >= 0 && cid < C_) ? cid : C_;
    sseg[g]  = seg;
    d_seg[b][g] = seg;
    int ky = (int)floorf(cy * 0.25f); ky = min(max(ky, 0), H_ - 1);
    int kx = (int)floorf(cx * 0.25f); kx = min(max(kx, 0), W_ - 1);
    d_kpy[b][g] = (unsigned char)ky;
    d_kpx[b][g] = (unsigned char)kx;
    __syncthreads();

    if (g == 0) {
        // slice_index = first-occurrence argmin of gt[:,0]
        float mn = scy[0]; int am = 0;
        for (int i = 1; i < G_; i++) if (scy[i] < mn) { mn = scy[i]; am = i; }
        d_nv[b] = am;
        // counting sort by class
        int cnt[C_ + 1];
        for (int c = 0; c <= C_; c++) cnt[c] = 0;
        for (int i = 0; i < am; i++) cnt[sseg[i]]++;
        int start[C_ + 2];
        start[0] = 0;
        for (int c = 0; c <= C_; c++) start[c + 1] = start[c] + cnt[c];
        for (int c = 0; c < C_ + 2; c++) d_start[b][c] = start[c];
        int pos[C_ + 1];
        for (int c = 0; c <= C_; c++) pos[c] = start[c];
        for (int i = 0; i < am; i++) d_order[b][pos[sseg[i]]++] = (unsigned char)i;
    }
}

// ---------------- main: one block per (b, y) row, thread = pixel x ----------------
__global__ __launch_bounds__(128) void main_kernel(const float* __restrict__ kpt,
                                                   const float* __restrict__ preg,
                                                   const float* __restrict__ fpn,
                                                   const float* __restrict__ masks) {
    int bid = blockIdx.x;
    int b = bid >> 7, y = bid & 127;
    int x = threadIdx.x;

    __shared__ float         skpt[C_][W_], sfpn[C_][W_];   // transposed, conflict-free reads
    __shared__ float4        sbox[G_];
    __shared__ float         ssfx[G_], sisx[G_], seyarg[G_];
    __shared__ unsigned char sorder[G_];
    __shared__ int           sstart[C_ + 2];
    __shared__ int           sActG[G_], sActC[G_];
    __shared__ float         sActT[G_], sActD[G_];
    __shared__ unsigned      skp[W_];
    __shared__ int           s_nAct, s_nv;
    __shared__ double        sacc[6][4];

    float yg = y + 0.5f, xg = x + 0.5f;

    // phase 0: zero/init
    if (x == 0) { s_nAct = 0; s_nv = d_nv[b]; }
    skp[x] = 0u;
    __syncthreads();
    int nv = s_nv;

    // phase 1: per-gt row constants, compaction, kp scatter, kpt/fpn staging
    if (x < G_) {
        float4 bb = d_box[b][x];
        sbox[x]   = bb;
        ssfx[x]   = d_sfx[b][x];
        sisx[x]   = d_isx[b][x];
        float dy  = (float)y - d_sfy[b][x];
        seyarg[x] = -dy * dy * d_isy[b][x];
        sorder[x] = d_order[b][x];
        if (x < nv) {
            float t = yg - bb.z, dd = bb.w - yg;
            if (t > 0.f && dd > 0.f) {
                int a = atomicAdd(&s_nAct, 1);
                sActG[a] = x; sActT[a] = t; sActD[a] = dd; sActC[a] = d_seg[b][x];
            }
            int seg = d_seg[b][x];
            if (seg < C_ && (int)d_kpy[b][x] == y)
                atomicOr(&skp[d_kpx[b][x]], 1u << seg);
        }
    }
    if (x < C_ + 2) sstart[x] = d_start[b][x];

    size_t rowoff = (size_t)(b * H_ + y) * W_;
    const float4* k4 = reinterpret_cast<const float4*>(kpt + rowoff * C_);
    const float4* f4 = reinterpret_cast<const float4*>(fpn + rowoff * C_);
#pragma unroll
    for (int i = x; i < W_ * C_ / 4; i += 128) {
        int xx = i / 5, c0 = (i % 5) * 4;
        float4 v = k4[i];
        skpt[c0][xx] = v.x; skpt[c0 + 1][xx] = v.y; skpt[c0 + 2][xx] = v.z; skpt[c0 + 3][xx] = v.w;
        float4 w = f4[i];
        sfpn[c0][xx] = w.x; sfpn[c0 + 1][xx] = w.y; sfpn[c0 + 2][xx] = w.z; sfpn[c0 + 3][xx] = w.w;
    }
    __syncthreads();

    int nA = s_nAct;
    const float* mrow = masks + rowoff * G_ + (size_t)x * G_;

    // ---- pass 1 (compacted): loc, area_min ----
    float area_min = (nA == G_) ? FLT_MAX : 1e8f;
    float loc = 0.f;
    for (int a = 0; a < nA; a++) {
        int g = sActG[a];
        float4 bb = sbox[g];
        float l = xg - bb.x, r = bb.y - xg;
        float m = __ldg(&mrow[g]);
        float hm = (l > 0.f && r > 0.f) ? m : 0.f;
        loc = fmaxf(loc, hm);
        area_min = fminf(area_min, area_pad_f(l, r, sActT[a], sActD[a], hm));
    }

    // ---- pass 2 (compacted): dist-mask maxima, per-class hg bitmask ----
    float dl = 0, dr = 0, dt = 0, db = 0;
    unsigned hgb = 0;
    for (int a = 0; a < nA; a++) {
        int g = sActG[a];
        float4 bb = sbox[g];
        float l = xg - bb.x, r = bb.y - xg;
        float t = sActT[a], d = sActD[a];
        float m = __ldg(&mrow[g]);
        float hm = (l > 0.f && r > 0.f) ? m : 0.f;
        float ap = area_pad_f(l, r, t, d, hm);
        if (ap == area_min) {
            float dm = loc;
            dl = fmaxf(dl, l * hm * dm);
            dr = fmaxf(dr, r * hm * dm);
            dt = fmaxf(dt, t * hm * dm);
            db = fmaxf(db, d * hm * dm);
            hgb |= 1u << sActC[a];
        }
    }
    if (loc == 0.f) hgb = 0;

    // ---- pass 3: per-class gaussian max + fused focal losses ----
    float iou_red = 0.f, grav = 0.f, hpos = 0.f, hneg = 0.f, shg = 0.f;
    unsigned kb = skp[x];
    float xf = (float)x;
    for (int c = 0; c <= C_; c++) {
        float rg = 0.f;
        int j1 = sstart[c + 1];
        for (int j = sstart[c]; j < j1; j++) {
            int g = sorder[j];
            float dx = xf - ssfx[g];
            float red = __expf(fmaf(-dx * dx, sisx[g], seyarg[g]));
            rg = fmaxf(rg, red);
        }
        iou_red = fmaxf(iou_red, rg);
        if (c < C_) {
            float hg = ((hgb >> c) & 1u) ? loc : 0.f;
            // gravity focal (keypoints)
            float p  = fminf(fmaxf(skpt[c][x], -30.f), 30.f);
            float e1 = __expf(-p);
            float L1 = __logf(1.f + e1);            // -log_sigmoid(p)
            float iv = __fdividef(1.f, 1.f + e1);   // sigmoid(p)
            float om = e1 * iv;                     // 1 - sigmoid(p)
            float q  = 1.f - rg; q = q * q; q = q * q;
            float neg = q * iv * iv * (p + L1);
            float pos = om * om * L1;
            grav += ((kb >> c) & 1u) ? pos : neg;
            // heatmap focal (fpn)
            float f   = fminf(fmaxf(sfpn[c][x], -30.f), 30.f);
            float e2  = __expf(-f);
            float L2  = __logf(1.f + e2);
            float iv2 = __fdividef(1.f, 1.f + e2);
            float om2 = e2 * iv2;
            hpos += om2 * om2 * L2 * hg;
            hneg += iv2 * iv2 * (f + L2);
            shg  += hg;
        }
    }

    // ---- IoU term ----
    float4 pv = reinterpret_cast<const float4*>(preg)[rowoff + x];
    float pl = pv.x, pr = pv.y, pt = pv.z, pb = pv.w;
    float inter = (fminf(dl, pl) + fminf(dr, pr)) * (fminf(dt, pt) + fminf(db, pb));
    float uni   = (dl + dr) * (dt + db) + (pl + pr) * (pt + pb) - inter;
    float iou   = inter / (uni + 1e-12f);
    float iou_t = -__logf(iou + 1e-12f) * loc * (iou_red * 4.f + 1.f);

    // ---- deterministic block reduction ----
    double v[6] = { (double)iou_t, (double)loc, (double)grav,
                    (double)hpos * 10.0, (double)hneg * 10.0, (double)shg };
#pragma unroll
    for (int off = 16; off; off >>= 1)
#pragma unroll
        for (int k = 0; k < 6; k++) v[k] += __shfl_down_sync(0xffffffffu, v[k], off);
    int w = x >> 5, lane = x & 31;
    if (lane == 0)
#pragma unroll
        for (int k = 0; k < 6; k++) sacc[k][w] = v[k];
    __syncthreads();
    if (x == 0) {
#pragma unroll
        for (int k = 0; k < 6; k++)
            d_partial[bid][k] = sacc[k][0] + sacc[k][1] + sacc[k][2] + sacc[k][3];
    }
}

// ---------------- final: deterministic combine ----------------
__global__ void final_kernel(float* __restrict__ out) {
    int t = threadIdx.x;   // 128 threads, thread t = row t
    __shared__ double sacc[6][4];
    double tot = 0.0;
    for (int b = 0; b < B_; b++) {
        double v[6];
#pragma unroll
        for (int k = 0; k < 6; k++) v[k] = d_partial[b * H_ + t][k];
#pragma unroll
        for (int off = 16; off; off >>= 1)
#pragma unroll
            for (int k = 0; k < 6; k++) v[k] += __shfl_down_sync(0xffffffffu, v[k], off);
        int w = t >> 5, lane = t & 31;
        __syncthreads();
        if (lane == 0)
#pragma unroll
            for (int k = 0; k < 6; k++) sacc[k][w] = v[k];
        __syncthreads();
        if (t == 0) {
            double iouS  = sacc[0][0] + sacc[0][1] + sacc[0][2] + sacc[0][3];
            double slocS = sacc[1][0] + sacc[1][1] + sacc[1][2] + sacc[1][3];
            double gravS = sacc[2][0] + sacc[2][1] + sacc[2][2] + sacc[2][3];
            double hposS = sacc[3][0] + sacc[3][1] + sacc[3][2] + sacc[3][3];
            double hnegS = sacc[4][0] + sacc[4][1] + sacc[4][2] + sacc[4][3];
            double shgS  = sacc[5][0] + sacc[5][1] + sacc[5][2] + sacc[5][3];
            double HWC = (double)(H_ * W_ * C_);
            double hm_loss = hnegS / (HWC - shgS);
            bool cond = (shgS != 0.0);
            double hm2 = hm_loss + hposS / (cond ? shgS : 1.0);
            double safe_loc = (slocS > 0.0) ? slocS : 1.0;
            double iou_out = cond ? (iouS / safe_loc) : 0.0;
            double nvf = (d_nv[b] > 1) ? (double)d_nv[b] : 1.0;
            double grav_out = cond ? (gravS / nvf) : 0.0;
            double total = cond ? (iou_out + grav_out + hm2) : hm_loss;
            tot += total;
        }
    }
    if (t == 0) out[0] = (float)(tot * (1.0 / B_));
}

// ---------------- launch ----------------
extern "C" void kernel_launch(void* const* d_in, const int* in_sizes, int n_in,
                              void* d_out, int out_size) {
    const float* keypoints = (const float*)d_in[0];
    const float* preg      = (const float*)d_in[1];
    const float* fpn       = (const float*)d_in[2];
    const float* gt        = (const float*)d_in[3];
    const float* masks     = (const float*)d_in[4];
    const float* sy        = (const float*)d_in[5];
    const float* sx        = (const float*)d_in[6];
    (void)in_sizes; (void)n_in; (void)out_size;

    prep_kernel<<<B_, G_>>>(gt, sy, sx);
    main_kernel<<<B_ * H_, 128>>>(keypoints, preg, fpn, masks);
    final_kernel<<<1, 128>>>((float*)d_out);
}